// round 2
// baseline (speedup 1.0000x reference)
#include <cuda_runtime.h>
#include <math.h>

// ---------------- problem constants ----------------
#define BN_ 16384
#define D_IN 1024
#define H1 512
#define H2 256
#define H3 128
#define FH 64
#define NDOM 4
#define EMB 16
#define BMROWS 128
#define BP 16896            // BN_ + NDOM*BMROWS (padded row count), 132 tiles of 128

// ---------------- scratch (device globals; no runtime alloc allowed) ----------------
__device__ float g_norm[(size_t)BP * D_IN];
__device__ float g_h1c[(size_t)BP * H1];
__device__ float g_h1d[(size_t)BP * H1];
__device__ float g_h2c[(size_t)BP * H2];
__device__ float g_h2d[(size_t)BP * H2];
__device__ float g_h3c[(size_t)BP * H3];
__device__ float g_h3d[(size_t)BP * H3];
__device__ int   g_perm[BP];
__device__ int   g_pdom[BP];
__device__ int   g_cnt[NDOM];
__device__ int   g_off[NDOM];
__device__ int   g_cur[NDOM];
__device__ float g_aux[NDOM];

// ---------------- sort infrastructure ----------------
__global__ void reset_kernel() {
    int i = blockIdx.x * blockDim.x + threadIdx.x;
    if (i < BP) { g_perm[i] = -1; g_pdom[i] = 0; }
    if (i < NDOM) g_cnt[i] = 0;
}

__global__ void count_kernel(const int* __restrict__ dids) {
    int i = blockIdx.x * blockDim.x + threadIdx.x;
    if (i < BN_) atomicAdd(&g_cnt[dids[i]], 1);
}

__global__ void offset_kernel() {
    if (threadIdx.x == 0) {
        int off = 0;
        for (int d = 0; d < NDOM; d++) {
            g_off[d] = off; g_cur[d] = off;
            off += (g_cnt[d] + BMROWS - 1) & ~(BMROWS - 1);
        }
    }
}

__global__ void scatter_kernel(const int* __restrict__ dids) {
    int i = blockIdx.x * blockDim.x + threadIdx.x;
    if (i < BN_) {
        int d = dids[i];
        int pos = atomicAdd(&g_cur[d], 1);
        g_perm[pos] = i;
    }
}

__global__ void pdom_kernel() {
    int p = blockIdx.x * blockDim.x + threadIdx.x;
    if (p < BP) {
        int dm = 0;
        #pragma unroll
        for (int d = 0; d < NDOM; d++) {
            int s = g_off[d];
            int e = s + ((g_cnt[d] + BMROWS - 1) & ~(BMROWS - 1));
            if (p >= s && p < e) dm = d;
        }
        g_pdom[p] = dm;
    }
}

// aux net depends only on domain id -> 4 scalars. 1 block, warp per domain.
__global__ void aux_kernel(const float* __restrict__ dom_emb,
                           const float* __restrict__ aW1, const float* __restrict__ ab1,
                           const float* __restrict__ aW2, const float* __restrict__ ab2) {
    int w = threadIdx.x >> 5;   // domain
    int j = threadIdx.x & 31;   // hidden unit (32)
    float s = ab1[j];
    #pragma unroll
    for (int i = 0; i < EMB; i++) s += dom_emb[w * EMB + i] * aW1[i * 32 + j];
    float v = fmaxf(s, 0.f) * aW2[j];
    #pragma unroll
    for (int o = 16; o; o >>= 1) v += __shfl_xor_sync(0xFFFFFFFFu, v, o);
    if (j == 0) g_aux[w] = v + ab2[0];
}

// ---------------- layernorm + domain affine, written in permuted order ----------------
__global__ __launch_bounds__(256) void ln_kernel(const float* __restrict__ x,
                                                 const int* __restrict__ dids,
                                                 const float* __restrict__ pnw,
                                                 const float* __restrict__ pnb) {
    int p = blockIdx.x;
    int tid = threadIdx.x;
    float* out = g_norm + (size_t)p * D_IN;
    int r = g_perm[p];
    if (r < 0) {
        float4 z = {0.f, 0.f, 0.f, 0.f};
        *(float4*)&out[tid * 4] = z;
        return;
    }
    const float* xr = x + (size_t)r * D_IN;
    float4 v = *(const float4*)&xr[tid * 4];
    float s = v.x + v.y + v.z + v.w;
    float q = v.x * v.x + v.y * v.y + v.z * v.z + v.w * v.w;
    #pragma unroll
    for (int o = 16; o; o >>= 1) {
        s += __shfl_xor_sync(0xFFFFFFFFu, s, o);
        q += __shfl_xor_sync(0xFFFFFFFFu, q, o);
    }
    __shared__ float ss[8], sq[8];
    __shared__ float smean, sinv;
    if ((tid & 31) == 0) { ss[tid >> 5] = s; sq[tid >> 5] = q; }
    __syncthreads();
    if (tid < 32) {
        s = (tid < 8) ? ss[tid] : 0.f;
        q = (tid < 8) ? sq[tid] : 0.f;
        #pragma unroll
        for (int o = 4; o; o >>= 1) {
            s += __shfl_xor_sync(0xFFFFFFFFu, s, o);
            q += __shfl_xor_sync(0xFFFFFFFFu, q, o);
        }
        if (tid == 0) {
            float mean = s * (1.f / D_IN);
            float var = q * (1.f / D_IN) - mean * mean;
            smean = mean;
            sinv = rsqrtf(var + 1e-5f);
        }
    }
    __syncthreads();
    int d = dids[r];
    float4 w = *(const float4*)&pnw[(size_t)d * D_IN + tid * 4];
    float4 b = *(const float4*)&pnb[(size_t)d * D_IN + tid * 4];
    float m = smean, inv = sinv;
    float4 o;
    o.x = (v.x - m) * inv * w.x + b.x;
    o.y = (v.y - m) * inv * w.y + b.y;
    o.z = (v.z - m) * inv * w.z + b.z;
    o.w = (v.w - m) * inv * w.w + b.w;
    *(float4*)&out[tid * 4] = o;
}

// ---------------- tiled GEMM: 128x128x16, 256 threads, 8x8 per thread ----------------
// grid.z = 0 -> center path, 1 -> domain path (weight/bias selected by block's domain)
template <int K, int N, bool RELU, int LAYER>
__global__ __launch_bounds__(256) void gemm_kernel(const float* __restrict__ Wc,
                                                   const float* __restrict__ Wd,
                                                   const float* __restrict__ bc,
                                                   const float* __restrict__ bd) {
    constexpr int BM = 128, BNT = 128, BK = 16;
    __shared__ float As[BK][BM];
    __shared__ float Bs[BK][BNT];

    const int tid = threadIdx.x;
    const int tx = tid & 15, ty = tid >> 4;
    const int by = blockIdx.y, bx = blockIdx.x;
    const int z = blockIdx.z;
    const int m0 = by * BM;
    const int n0 = bx * BNT;

    const float* A; float* C;
    if constexpr (LAYER == 1) { A = g_norm;               C = z ? g_h1d : g_h1c; }
    if constexpr (LAYER == 2) { A = z ? g_h1d : g_h1c;    C = z ? g_h2d : g_h2c; }
    if constexpr (LAYER == 3) { A = z ? g_h2d : g_h2c;    C = z ? g_h3d : g_h3c; }

    const float* W; const float* bias;
    if (z == 0) { W = Wc; bias = bc; }
    else {
        int dom = g_pdom[m0];
        W = Wd + (size_t)dom * K * N;
        bias = bd + (size_t)dom * N;
    }

    float acc[8][8];
    #pragma unroll
    for (int i = 0; i < 8; i++)
        #pragma unroll
        for (int j = 0; j < 8; j++) acc[i][j] = 0.f;

    for (int k0 = 0; k0 < K; k0 += BK) {
        #pragma unroll
        for (int e = 0; e < 2; e++) {
            int lin = tid + e * 256;
            int arow = lin >> 2, ac = (lin & 3) * 4;
            float4 v = *(const float4*)&A[(size_t)(m0 + arow) * K + k0 + ac];
            As[ac + 0][arow] = v.x;
            As[ac + 1][arow] = v.y;
            As[ac + 2][arow] = v.z;
            As[ac + 3][arow] = v.w;
            int bk = lin >> 5, bn = (lin & 31) * 4;
            *(float4*)&Bs[bk][bn] = *(const float4*)&W[(size_t)(k0 + bk) * N + n0 + bn];
        }
        __syncthreads();
        #pragma unroll
        for (int kk = 0; kk < BK; kk++) {
            float a[8], b[8];
            *(float4*)&a[0] = *(const float4*)&As[kk][ty * 4];
            *(float4*)&a[4] = *(const float4*)&As[kk][ty * 4 + 64];
            *(float4*)&b[0] = *(const float4*)&Bs[kk][tx * 4];
            *(float4*)&b[4] = *(const float4*)&Bs[kk][tx * 4 + 64];
            #pragma unroll
            for (int i = 0; i < 8; i++)
                #pragma unroll
                for (int j = 0; j < 8; j++)
                    acc[i][j] += a[i] * b[j];
        }
        __syncthreads();
    }

    float bj[8];
    #pragma unroll
    for (int j = 0; j < 8; j++) {
        int cn = tx * 4 + (j & 3) + ((j >> 2) * 64);
        bj[j] = bias[n0 + cn];
    }
    #pragma unroll
    for (int i = 0; i < 8; i++) {
        int m = m0 + ty * 4 + (i & 3) + ((i >> 2) * 64);
        float4 o0, o1;
        o0.x = acc[i][0] + bj[0]; o0.y = acc[i][1] + bj[1];
        o0.z = acc[i][2] + bj[2]; o0.w = acc[i][3] + bj[3];
        o1.x = acc[i][4] + bj[4]; o1.y = acc[i][5] + bj[5];
        o1.z = acc[i][6] + bj[6]; o1.w = acc[i][7] + bj[7];
        if (RELU) {
            o0.x = fmaxf(o0.x, 0.f); o0.y = fmaxf(o0.y, 0.f);
            o0.z = fmaxf(o0.z, 0.f); o0.w = fmaxf(o0.w, 0.f);
            o1.x = fmaxf(o1.x, 0.f); o1.y = fmaxf(o1.y, 0.f);
            o1.z = fmaxf(o1.z, 0.f); o1.w = fmaxf(o1.w, 0.f);
        }
        *(float4*)&C[(size_t)m * N + n0 + tx * 4]      = o0;
        *(float4*)&C[(size_t)m * N + n0 + tx * 4 + 64] = o1;
    }
}

// ---------------- fuse + final MLP + aux + sigmoid (one warp per row) ----------------
__global__ __launch_bounds__(256) void final_kernel(const float* __restrict__ fW1,
                                                    const float* __restrict__ fb1,
                                                    const float* __restrict__ fW2,
                                                    const float* __restrict__ fb2,
                                                    float* __restrict__ out) {
    __shared__ float sW1[H3 * FH];   // 128*64 = 32KB
    __shared__ float sb1[FH], sW2[FH];
    __shared__ float sf[8][H3];

    int tid = threadIdx.x;
    for (int i = tid; i < H3 * FH; i += 256) sW1[i] = fW1[i];
    if (tid < FH) { sb1[tid] = fb1[tid]; sW2[tid] = fW2[tid]; }
    __syncthreads();

    int w = tid >> 5, lane = tid & 31;
    int p = blockIdx.x * 8 + w;
    int r = g_perm[p];

    #pragma unroll
    for (int q = 0; q < 4; q++) {
        int i = q * 32 + lane;
        float c = g_h3c[(size_t)p * H3 + i];
        float d = g_h3d[(size_t)p * H3 + i];
        sf[w][i] = c * tanhf(d);
    }
    __syncwarp();

    float acc = 0.f;
    #pragma unroll
    for (int jj = 0; jj < 2; jj++) {
        int j = jj * 32 + lane;
        float h = sb1[j];
        #pragma unroll 8
        for (int i = 0; i < H3; i++) h += sf[w][i] * sW1[i * FH + j];
        acc += fmaxf(h, 0.f) * sW2[j];
    }
    #pragma unroll
    for (int o = 16; o; o >>= 1) acc += __shfl_xor_sync(0xFFFFFFFFu, acc, o);

    if (lane == 0 && r >= 0) {
        float v = acc + fb2[0] + g_aux[g_pdom[p]];
        out[r] = 1.f / (1.f + expf(-v));
    }
}

// ---------------- launch ----------------
extern "C" void kernel_launch(void* const* d_in, const int* in_sizes, int n_in,
                              void* d_out, int out_size) {
    const float* x      = (const float*)d_in[0];
    const int*   dids   = (const int*)  d_in[1];
    const float* pnw    = (const float*)d_in[2];
    const float* pnb    = (const float*)d_in[3];
    const float* cW1    = (const float*)d_in[4];
    const float* cb1    = (const float*)d_in[5];
    const float* cW2    = (const float*)d_in[6];
    const float* cb2    = (const float*)d_in[7];
    const float* cW3    = (const float*)d_in[8];
    const float* cb3    = (const float*)d_in[9];
    const float* dW1    = (const float*)d_in[10];
    const float* db1    = (const float*)d_in[11];
    const float* dW2    = (const float*)d_in[12];
    const float* db2    = (const float*)d_in[13];
    const float* dW3    = (const float*)d_in[14];
    const float* db3    = (const float*)d_in[15];
    const float* fW1    = (const float*)d_in[16];
    const float* fb1    = (const float*)d_in[17];
    const float* fW2    = (const float*)d_in[18];
    const float* fb2    = (const float*)d_in[19];
    const float* dom_emb= (const float*)d_in[20];
    const float* aW1    = (const float*)d_in[21];
    const float* ab1    = (const float*)d_in[22];
    const float* aW2    = (const float*)d_in[23];
    const float* ab2    = (const float*)d_in[24];
    float* out = (float*)d_out;

    reset_kernel<<<(BP + 255) / 256, 256>>>();
    count_kernel<<<(BN_ + 255) / 256, 256>>>(dids);
    offset_kernel<<<1, 32>>>();
    scatter_kernel<<<(BN_ + 255) / 256, 256>>>(dids);
    pdom_kernel<<<(BP + 255) / 256, 256>>>();
    aux_kernel<<<1, 128>>>(dom_emb, aW1, ab1, aW2, ab2);
    ln_kernel<<<BP, 256>>>(x, dids, pnw, pnb);

    gemm_kernel<D_IN, H1, true,  1><<<dim3(H1 / 128, BP / 128, 2), 256>>>(cW1, dW1, cb1, db1);
    gemm_kernel<H1,   H2, true,  2><<<dim3(H2 / 128, BP / 128, 2), 256>>>(cW2, dW2, cb2, db2);
    gemm_kernel<H2,   H3, false, 3><<<dim3(H3 / 128, BP / 128, 2), 256>>>(cW3, dW3, cb3, db3);

    final_kernel<<<BP / 8, 256>>>(fW1, fb1, fW2, fb2, out);
}